// round 14
// baseline (speedup 1.0000x reference)
#include <cuda_runtime.h>
#include <cuda_fp16.h>
#include <stdint.h>
#include <math.h>

#define MAXN 100000
#define MAXE 1600000
#define HDIM 64
#define CAP 128          // per-node bucket capacity (Poisson(16) tail ~ 0)

// ---------------- device scratch (no allocations allowed) ----------------
__device__ int    g_is64;
__device__ int    g_srcs[(size_t)MAXN * CAP];  // bucketed sources, 51.2 MB
__device__ int    g_cur [MAXN];                // fill cursor == in-degree
__device__ float  g_dinv[MAXN];
__device__ __half g_yh[(size_t)MAXN * HDIM];   // UNSCALED xW, fp16
__device__ __half g_h [(size_t)MAXN * HDIM];   // layer activations, fp16

// ---------------- zero cursors + dtype detection ---------------------------
__global__ void zero_detect(const int* __restrict__ ei, int N) {
    int i = blockIdx.x * blockDim.x + threadIdx.x;
    if (i < N) g_cur[i] = 0;
    if (i == 0) {
        int is64 = 1;
        for (int t = 1; t < 128; t += 2)
            if (ei[t] != 0) { is64 = 0; break; }
        g_is64 = is64;
    }
}

// ---------------- dinv from cursor (== degree) ------------------------------
__global__ void dinv_kernel(int N) {
    int i = blockIdx.x * blockDim.x + threadIdx.x;
    if (i < N) {
        int d = g_cur[i];
        if (d > CAP) d = CAP;        // saturate (never hit in practice)
        g_cur[i] = d;
        g_dinv[i] = rsqrtf((float)(d + 1));
    }
}

// ---------------- GEMM device body: Yh = fp16(X @ W), unscaled -------------
// A streamed directly from global; W transposed in smem (stride K+8).
template<int K, bool XHALF>
__device__ __forceinline__ void gemm_body(const float* __restrict__ Xf,
                                          const float* __restrict__ Wf,
                                          int N, int tile, __half* Wt) {
    constexpr int STRIDE = K + 8;  // halves

    int tid = threadIdx.x;
    int warp = tid >> 5, lane = tid & 31;
    int row0 = tile * 128;
    int wrow = warp * 16;
    int r = lane >> 2;   // 0..7
    int c = lane & 3;    // 0..3

    #pragma unroll
    for (int i = tid; i < K * 16; i += 256) {
        int kk = i >> 4, nn = (i & 15) * 4;
        float4 w = *(const float4*)(Wf + (size_t)kk * 64 + nn);
        Wt[(nn + 0) * STRIDE + kk] = __float2half_rn(w.x);
        Wt[(nn + 1) * STRIDE + kk] = __float2half_rn(w.y);
        Wt[(nn + 2) * STRIDE + kk] = __float2half_rn(w.z);
        Wt[(nn + 3) * STRIDE + kk] = __float2half_rn(w.w);
    }
    __syncthreads();

    int gr0 = row0 + wrow + r;
    int gr1 = gr0 + 8;
    bool v0 = gr0 < N, v1 = gr1 < N;

    float acc[8][4] = {};

    #pragma unroll
    for (int ks = 0; ks < K / 16; ks++) {
        int k0 = ks * 16 + 2 * c;
        uint32_t a0 = 0, a1 = 0, a2 = 0, a3 = 0;
        if (!XHALF) {
            if (v0) {
                const float* xp = Xf + (size_t)gr0 * K + k0;
                float2 f0 = *(const float2*)xp;
                float2 f2 = *(const float2*)(xp + 8);
                __half2 p0 = __floats2half2_rn(f0.x, f0.y);
                __half2 p2 = __floats2half2_rn(f2.x, f2.y);
                a0 = *(uint32_t*)&p0; a2 = *(uint32_t*)&p2;
            }
            if (v1) {
                const float* xp = Xf + (size_t)gr1 * K + k0;
                float2 f1 = *(const float2*)xp;
                float2 f3 = *(const float2*)(xp + 8);
                __half2 p1 = __floats2half2_rn(f1.x, f1.y);
                __half2 p3 = __floats2half2_rn(f3.x, f3.y);
                a1 = *(uint32_t*)&p1; a3 = *(uint32_t*)&p3;
            }
        } else {
            if (v0) {
                const __half* xp = g_h + (size_t)gr0 * 64 + k0;
                a0 = *(const uint32_t*)xp;
                a2 = *(const uint32_t*)(xp + 8);
            }
            if (v1) {
                const __half* xp = g_h + (size_t)gr1 * 64 + k0;
                a1 = *(const uint32_t*)xp;
                a3 = *(const uint32_t*)(xp + 8);
            }
        }
        #pragma unroll
        for (int j = 0; j < 8; j++) {
            uint32_t b0 = *(const uint32_t*)&Wt[(j * 8 + r) * STRIDE + k0];
            uint32_t b1 = *(const uint32_t*)&Wt[(j * 8 + r) * STRIDE + k0 + 8];
            asm volatile(
                "mma.sync.aligned.m16n8k16.row.col.f32.f16.f16.f32 "
                "{%0,%1,%2,%3}, {%4,%5,%6,%7}, {%8,%9}, {%0,%1,%2,%3};"
                : "+f"(acc[j][0]), "+f"(acc[j][1]),
                  "+f"(acc[j][2]), "+f"(acc[j][3])
                : "r"(a0), "r"(a1), "r"(a2), "r"(a3), "r"(b0), "r"(b1));
        }
    }

    #pragma unroll
    for (int j = 0; j < 8; j++) {
        int col = j * 8 + 2 * c;
        if (v0)
            *(__half2*)&g_yh[(size_t)gr0 * 64 + col] =
                __floats2half2_rn(acc[j][0], acc[j][1]);
        if (v1)
            *(__half2*)&g_yh[(size_t)gr1 * 64 + col] =
                __floats2half2_rn(acc[j][2], acc[j][3]);
    }
}

// ---------------- fused: GEMM1 tiles || edge placement ----------------------
// gemm blocks first (long pole starts first), place blocks after.
__global__ void __launch_bounds__(256)
fused_gemm1_place(const float* __restrict__ Xf, const float* __restrict__ Wf,
                  int N, int nb_gm, const void* __restrict__ ei, int E) {
    __shared__ __half Wt[64 * (128 + 8)];
    if ((int)blockIdx.x < nb_gm) {
        gemm_body<128, false>(Xf, Wf, N, blockIdx.x, Wt);
    } else {
        int e = (blockIdx.x - nb_gm) * 256 + threadIdx.x;
        if (e >= E) return;
        int r, c;
        if (g_is64) {
            const long long* p = (const long long*)ei;
            r = (int)p[e]; c = (int)p[e + E];
        } else {
            const int* p = (const int*)ei;
            r = p[e]; c = p[e + E];
        }
        int pos = atomicAdd(&g_cur[c], 1);
        if (pos < CAP) g_srcs[(size_t)c * CAP + pos] = r;
    }
}

// ---------------- GEMM2 (unscaled) ------------------------------------------
__global__ void __launch_bounds__(256)
gemm2_kernel(const float* __restrict__ Wf, int N) {
    __shared__ __half Wt[64 * (64 + 8)];
    gemm_body<64, true>(nullptr, Wf, N, blockIdx.x, Wt);
}

// ---------------- aggregation: warp/node, 4 edges/LDG, per-edge dinv -------
template<bool FINAL>
__global__ void aggregate_kernel(const float* __restrict__ bias,
                                 const float* __restrict__ Wfc,
                                 const float* __restrict__ bfc,
                                 float* __restrict__ out, int N) {
    int node = blockIdx.x * 8 + (threadIdx.x >> 5);
    if (node >= N) return;
    int lane = threadIdx.x & 31;
    int q = lane >> 3;       // quarter 0..3
    int sub = lane & 7;      // covers cols [sub*8, sub*8+8)

    int cnt = g_cur[node];
    float dvn = g_dinv[node];

    float acc[8] = {};

    // self loop counted once (quarter 0): y[node]*dinv[node]
    if (q == 0) {
        uint4 sv = *(const uint4*)(g_yh + (size_t)node * 64 + sub * 8);
        const __half2* hp = (const __half2*)&sv;
        #pragma unroll
        for (int t = 0; t < 4; t++) {
            float2 f = __half22float2(hp[t]);
            acc[2 * t]     = f.x * dvn;
            acc[2 * t + 1] = f.y * dvn;
        }
    }

    int m = (cnt - q + 3) >> 2;                       // slots for this quarter
    const int* sp = g_srcs + (size_t)node * CAP + q;  // stride-4 walk

    int j = 0;
    for (; j + 1 < m; j += 2) {
        int s0 = __ldg(sp + 4 * j);
        int s1 = __ldg(sp + 4 * j + 4);
        float dv0 = __ldg(&g_dinv[s0]);
        float dv1 = __ldg(&g_dinv[s1]);
        uint4 v0 = *(const uint4*)(g_yh + (size_t)s0 * 64 + sub * 8);
        uint4 v1 = *(const uint4*)(g_yh + (size_t)s1 * 64 + sub * 8);
        const __half2* h0 = (const __half2*)&v0;
        const __half2* h1 = (const __half2*)&v1;
        #pragma unroll
        for (int t = 0; t < 4; t++) {
            float2 f0 = __half22float2(h0[t]);
            float2 f1 = __half22float2(h1[t]);
            acc[2 * t]     = fmaf(f0.x, dv0, fmaf(f1.x, dv1, acc[2 * t]));
            acc[2 * t + 1] = fmaf(f0.y, dv0, fmaf(f1.y, dv1, acc[2 * t + 1]));
        }
    }
    if (j < m) {
        int s0 = __ldg(sp + 4 * j);
        float dv0 = __ldg(&g_dinv[s0]);
        uint4 v0 = *(const uint4*)(g_yh + (size_t)s0 * 64 + sub * 8);
        const __half2* h0 = (const __half2*)&v0;
        #pragma unroll
        for (int t = 0; t < 4; t++) {
            float2 f0 = __half22float2(h0[t]);
            acc[2 * t]     = fmaf(f0.x, dv0, acc[2 * t]);
            acc[2 * t + 1] = fmaf(f0.y, dv0, acc[2 * t + 1]);
        }
    }

    #pragma unroll
    for (int t = 0; t < 8; t++) {
        acc[t] += __shfl_xor_sync(0xffffffffu, acc[t], 8);
        acc[t] += __shfl_xor_sync(0xffffffffu, acc[t], 16);
    }

    float4 bb0 = *(const float4*)(bias + sub * 8);
    float4 bb1 = *(const float4*)(bias + sub * 8 + 4);
    float h[8];
    h[0] = fmaxf(fmaf(acc[0], dvn, bb0.x), 0.f);
    h[1] = fmaxf(fmaf(acc[1], dvn, bb0.y), 0.f);
    h[2] = fmaxf(fmaf(acc[2], dvn, bb0.z), 0.f);
    h[3] = fmaxf(fmaf(acc[3], dvn, bb0.w), 0.f);
    h[4] = fmaxf(fmaf(acc[4], dvn, bb1.x), 0.f);
    h[5] = fmaxf(fmaf(acc[5], dvn, bb1.y), 0.f);
    h[6] = fmaxf(fmaf(acc[6], dvn, bb1.z), 0.f);
    h[7] = fmaxf(fmaf(acc[7], dvn, bb1.w), 0.f);

    if (!FINAL) {
        if (q == 0) {
            __half2 p[4];
            #pragma unroll
            for (int t = 0; t < 4; t++)
                p[t] = __floats2half2_rn(h[2 * t], h[2 * t + 1]);
            *(uint4*)(g_h + (size_t)node * 64 + sub * 8) = *(uint4*)p;
        }
    } else {
        float4 w0 = *(const float4*)(Wfc + sub * 8);
        float4 w1 = *(const float4*)(Wfc + sub * 8 + 4);
        float v = h[0] * w0.x + h[1] * w0.y + h[2] * w0.z + h[3] * w0.w
                + h[4] * w1.x + h[5] * w1.y + h[6] * w1.z + h[7] * w1.w;
        v += __shfl_down_sync(0xffffffffu, v, 4);
        v += __shfl_down_sync(0xffffffffu, v, 2);
        v += __shfl_down_sync(0xffffffffu, v, 1);
        if (lane == 0) {
            float z = v + __ldg(&bfc[0]);
            out[node] = 1.0f / (1.0f + expf(-z));
        }
    }
}

// ---------------- launch ----------------------------------------------------
extern "C" void kernel_launch(void* const* d_in, const int* in_sizes, int n_in,
                              void* d_out, int out_size) {
    const float* x   = (const float*)d_in[0];
    const void*  ei  = d_in[1];
    const float* W1  = (const float*)d_in[2];
    const float* b1  = (const float*)d_in[3];
    const float* W2  = (const float*)d_in[4];
    const float* b2  = (const float*)d_in[5];
    const float* Wfc = (const float*)d_in[6];
    const float* bfc = (const float*)d_in[7];
    float* out = (float*)d_out;

    int N = in_sizes[0] / 128;
    int E = in_sizes[1] / 2;
    if (N > MAXN) N = MAXN;
    if (E > MAXE) E = MAXE;

    const int TB = 256;
    int nb_N  = (N + TB - 1) / TB;
    int nb_E  = (E + TB - 1) / TB;
    int nb_GM = (N + 127) / 128;
    int nb_AG = (N + 7) / 8;

    zero_detect<<<nb_N, TB>>>((const int*)ei, N);

    // layer 1 GEMM overlapped with edge placement (independent work)
    fused_gemm1_place<<<nb_GM + nb_E, 256>>>(x, W1, N, nb_GM, ei, E);
    dinv_kernel<<<nb_N, TB>>>(N);
    aggregate_kernel<false><<<nb_AG, 256>>>(b1, nullptr, nullptr, nullptr, N);

    // layer 2
    gemm2_kernel<<<nb_GM, 256>>>(W2, N);
    aggregate_kernel<true><<<nb_AG, 256>>>(b2, Wfc, bfc, out, N);
}

// round 15
// speedup vs baseline: 1.0458x; 1.0458x over previous
#include <cuda_runtime.h>
#include <cuda_fp16.h>
#include <stdint.h>
#include <math.h>

#define MAXN 100000
#define MAXE 1600000
#define HDIM 64
#define CAP 128          // per-node bucket capacity (Poisson(16) tail ~ 0)

// ---------------- device scratch (no allocations allowed) ----------------
__device__ int    g_is64;
__device__ int    g_srcs[(size_t)MAXN * CAP];  // bucketed sources, 51.2 MB
__device__ int    g_cur [MAXN];                // fill cursor == in-degree
__device__ float  g_dinv[MAXN];
__device__ __half g_yh[(size_t)MAXN * HDIM];   // dinv-scaled xW, fp16
__device__ __half g_h [(size_t)MAXN * HDIM];   // layer activations, fp16

// ---------------- zero cursors + dtype detection ---------------------------
__global__ void zero_detect(const int* __restrict__ ei, int N) {
    int i = blockIdx.x * blockDim.x + threadIdx.x;
    if (i < N) g_cur[i] = 0;
    if (i == 0) {
        int is64 = 1;
        for (int t = 1; t < 128; t += 2)
            if (ei[t] != 0) { is64 = 0; break; }
        g_is64 = is64;
    }
}

// ---------------- direct bucket placement (one pass over edges) ------------
__global__ void place_direct(const void* __restrict__ ei, int E) {
    int e = blockIdx.x * blockDim.x + threadIdx.x;
    if (e >= E) return;
    int r, c;
    if (g_is64) {
        const long long* p = (const long long*)ei;
        r = (int)p[e]; c = (int)p[e + E];
    } else {
        const int* p = (const int*)ei;
        r = p[e]; c = p[e + E];
    }
    int pos = atomicAdd(&g_cur[c], 1);
    if (pos < CAP) g_srcs[(size_t)c * CAP + pos] = r;
}

// ---------------- dinv from cursor (== degree) ------------------------------
__global__ void dinv_kernel(int N) {
    int i = blockIdx.x * blockDim.x + threadIdx.x;
    if (i < N) {
        int d = g_cur[i];
        if (d > CAP) d = CAP;        // saturate (never hit in practice)
        g_cur[i] = d;
        g_dinv[i] = rsqrtf((float)(d + 1));
    }
}

// ---------------- tensor-core GEMM: Yh = fp16((X @ W) * dinv) --------------
// A streamed directly from global; W transposed in smem (stride K+8).
template<int K, bool XHALF>
__global__ void __launch_bounds__(256)
gemm_mma(const float* __restrict__ Xf, const float* __restrict__ Wf, int N) {
    constexpr int STRIDE = K + 8;  // halves
    __shared__ __half Wt[64 * STRIDE];   // Wt[n][k] = W[k][n]

    int tid = threadIdx.x;
    int warp = tid >> 5, lane = tid & 31;
    int row0 = blockIdx.x * 128;
    int wrow = warp * 16;
    int r = lane >> 2;   // 0..7
    int c = lane & 3;    // 0..3

    #pragma unroll
    for (int i = tid; i < K * 16; i += 256) {
        int kk = i >> 4, nn = (i & 15) * 4;
        float4 w = *(const float4*)(Wf + (size_t)kk * 64 + nn);
        Wt[(nn + 0) * STRIDE + kk] = __float2half_rn(w.x);
        Wt[(nn + 1) * STRIDE + kk] = __float2half_rn(w.y);
        Wt[(nn + 2) * STRIDE + kk] = __float2half_rn(w.z);
        Wt[(nn + 3) * STRIDE + kk] = __float2half_rn(w.w);
    }
    __syncthreads();

    int gr0 = row0 + wrow + r;
    int gr1 = gr0 + 8;
    bool v0 = gr0 < N, v1 = gr1 < N;

    float acc[8][4] = {};

    #pragma unroll
    for (int ks = 0; ks < K / 16; ks++) {
        int k0 = ks * 16 + 2 * c;
        uint32_t a0 = 0, a1 = 0, a2 = 0, a3 = 0;
        if (!XHALF) {
            if (v0) {
                const float* xp = Xf + (size_t)gr0 * K + k0;
                float2 f0 = *(const float2*)xp;
                float2 f2 = *(const float2*)(xp + 8);
                __half2 p0 = __floats2half2_rn(f0.x, f0.y);
                __half2 p2 = __floats2half2_rn(f2.x, f2.y);
                a0 = *(uint32_t*)&p0; a2 = *(uint32_t*)&p2;
            }
            if (v1) {
                const float* xp = Xf + (size_t)gr1 * K + k0;
                float2 f1 = *(const float2*)xp;
                float2 f3 = *(const float2*)(xp + 8);
                __half2 p1 = __floats2half2_rn(f1.x, f1.y);
                __half2 p3 = __floats2half2_rn(f3.x, f3.y);
                a1 = *(uint32_t*)&p1; a3 = *(uint32_t*)&p3;
            }
        } else {
            if (v0) {
                const __half* xp = g_h + (size_t)gr0 * 64 + k0;
                a0 = *(const uint32_t*)xp;
                a2 = *(const uint32_t*)(xp + 8);
            }
            if (v1) {
                const __half* xp = g_h + (size_t)gr1 * 64 + k0;
                a1 = *(const uint32_t*)xp;
                a3 = *(const uint32_t*)(xp + 8);
            }
        }
        #pragma unroll
        for (int j = 0; j < 8; j++) {
            uint32_t b0 = *(const uint32_t*)&Wt[(j * 8 + r) * STRIDE + k0];
            uint32_t b1 = *(const uint32_t*)&Wt[(j * 8 + r) * STRIDE + k0 + 8];
            asm volatile(
                "mma.sync.aligned.m16n8k16.row.col.f32.f16.f16.f32 "
                "{%0,%1,%2,%3}, {%4,%5,%6,%7}, {%8,%9}, {%0,%1,%2,%3};"
                : "+f"(acc[j][0]), "+f"(acc[j][1]),
                  "+f"(acc[j][2]), "+f"(acc[j][3])
                : "r"(a0), "r"(a1), "r"(a2), "r"(a3), "r"(b0), "r"(b1));
        }
    }

    float d0 = v0 ? g_dinv[gr0] : 0.f;
    float d1 = v1 ? g_dinv[gr1] : 0.f;
    #pragma unroll
    for (int j = 0; j < 8; j++) {
        int col = j * 8 + 2 * c;
        if (v0)
            *(__half2*)&g_yh[(size_t)gr0 * 64 + col] =
                __floats2half2_rn(acc[j][0] * d0, acc[j][1] * d0);
        if (v1)
            *(__half2*)&g_yh[(size_t)gr1 * 64 + col] =
                __floats2half2_rn(acc[j][2] * d1, acc[j][3] * d1);
    }
}

// ---------------- aggregation: warp/node, 4 edges/LDG, fp16 tree sum -------
// Quarter-warp q (8 lanes) handles bucket slots q, q+4, ...; each lane loads
// 16B (8 halves). Main loop: 4 edges summed pairwise in fp16 (HADD2 tree),
// converted+accumulated to fp32 once per 4 edges. Pair + single remainders.
template<bool FINAL>
__global__ void aggregate_kernel(const float* __restrict__ bias,
                                 const float* __restrict__ Wfc,
                                 const float* __restrict__ bfc,
                                 float* __restrict__ out, int N) {
    int node = blockIdx.x * 8 + (threadIdx.x >> 5);
    if (node >= N) return;
    int lane = threadIdx.x & 31;
    int q = lane >> 3;       // quarter 0..3
    int sub = lane & 7;      // covers cols [sub*8, sub*8+8)

    int cnt = g_cur[node];

    float acc[8] = {};

    // self loop counted once (quarter 0)
    if (q == 0) {
        uint4 sv = *(const uint4*)(g_yh + (size_t)node * 64 + sub * 8);
        const __half2* hp = (const __half2*)&sv;
        #pragma unroll
        for (int t = 0; t < 4; t++) {
            float2 f = __half22float2(hp[t]);
            acc[2 * t]     = f.x;
            acc[2 * t + 1] = f.y;
        }
    }

    int m = (cnt - q + 3) >> 2;                       // slots for this quarter
    const int* sp = g_srcs + (size_t)node * CAP + q;  // stride-4 walk

    int j = 0;
    for (; j + 3 < m; j += 4) {
        int s0 = __ldg(sp + 4 * j);
        int s1 = __ldg(sp + 4 * j + 4);
        int s2 = __ldg(sp + 4 * j + 8);
        int s3 = __ldg(sp + 4 * j + 12);
        uint4 v0 = *(const uint4*)(g_yh + (size_t)s0 * 64 + sub * 8);
        uint4 v1 = *(const uint4*)(g_yh + (size_t)s1 * 64 + sub * 8);
        uint4 v2 = *(const uint4*)(g_yh + (size_t)s2 * 64 + sub * 8);
        uint4 v3 = *(const uint4*)(g_yh + (size_t)s3 * 64 + sub * 8);
        const __half2* h0 = (const __half2*)&v0;
        const __half2* h1 = (const __half2*)&v1;
        const __half2* h2 = (const __half2*)&v2;
        const __half2* h3 = (const __half2*)&v3;
        #pragma unroll
        for (int t = 0; t < 4; t++) {
            __half2 u = __hadd2(__hadd2(h0[t], h1[t]), __hadd2(h2[t], h3[t]));
            float2 f = __half22float2(u);
            acc[2 * t]     += f.x;
            acc[2 * t + 1] += f.y;
        }
    }
    if (j + 1 < m) {
        int s0 = __ldg(sp + 4 * j);
        int s1 = __ldg(sp + 4 * j + 4);
        uint4 v0 = *(const uint4*)(g_yh + (size_t)s0 * 64 + sub * 8);
        uint4 v1 = *(const uint4*)(g_yh + (size_t)s1 * 64 + sub * 8);
        const __half2* h0 = (const __half2*)&v0;
        const __half2* h1 = (const __half2*)&v1;
        #pragma unroll
        for (int t = 0; t < 4; t++) {
            float2 f = __half22float2(__hadd2(h0[t], h1[t]));
            acc[2 * t]     += f.x;
            acc[2 * t + 1] += f.y;
        }
        j += 2;
    }
    if (j < m) {
        int s0 = __ldg(sp + 4 * j);
        uint4 v0 = *(const uint4*)(g_yh + (size_t)s0 * 64 + sub * 8);
        const __half2* h0 = (const __half2*)&v0;
        #pragma unroll
        for (int t = 0; t < 4; t++) {
            float2 f = __half22float2(h0[t]);
            acc[2 * t]     += f.x;
            acc[2 * t + 1] += f.y;
        }
    }

    #pragma unroll
    for (int t = 0; t < 8; t++) {
        acc[t] += __shfl_xor_sync(0xffffffffu, acc[t], 8);
        acc[t] += __shfl_xor_sync(0xffffffffu, acc[t], 16);
    }

    float dv = g_dinv[node];
    float4 bb0 = *(const float4*)(bias + sub * 8);
    float4 bb1 = *(const float4*)(bias + sub * 8 + 4);
    float h[8];
    h[0] = fmaxf(fmaf(acc[0], dv, bb0.x), 0.f);
    h[1] = fmaxf(fmaf(acc[1], dv, bb0.y), 0.f);
    h[2] = fmaxf(fmaf(acc[2], dv, bb0.z), 0.f);
    h[3] = fmaxf(fmaf(acc[3], dv, bb0.w), 0.f);
    h[4] = fmaxf(fmaf(acc[4], dv, bb1.x), 0.f);
    h[5] = fmaxf(fmaf(acc[5], dv, bb1.y), 0.f);
    h[6] = fmaxf(fmaf(acc[6], dv, bb1.z), 0.f);
    h[7] = fmaxf(fmaf(acc[7], dv, bb1.w), 0.f);

    if (!FINAL) {
        if (q == 0) {
            __half2 p[4];
            #pragma unroll
            for (int t = 0; t < 4; t++)
                p[t] = __floats2half2_rn(h[2 * t], h[2 * t + 1]);
            *(uint4*)(g_h + (size_t)node * 64 + sub * 8) = *(uint4*)p;
        }
    } else {
        float4 w0 = *(const float4*)(Wfc + sub * 8);
        float4 w1 = *(const float4*)(Wfc + sub * 8 + 4);
        float v = h[0] * w0.x + h[1] * w0.y + h[2] * w0.z + h[3] * w0.w
                + h[4] * w1.x + h[5] * w1.y + h[6] * w1.z + h[7] * w1.w;
        v += __shfl_down_sync(0xffffffffu, v, 4);
        v += __shfl_down_sync(0xffffffffu, v, 2);
        v += __shfl_down_sync(0xffffffffu, v, 1);
        if (lane == 0) {
            float z = v + __ldg(&bfc[0]);
            out[node] = 1.0f / (1.0f + expf(-z));
        }
    }
}

// ---------------- launch ----------------------------------------------------
extern "C" void kernel_launch(void* const* d_in, const int* in_sizes, int n_in,
                              void* d_out, int out_size) {
    const float* x   = (const float*)d_in[0];
    const void*  ei  = d_in[1];
    const float* W1  = (const float*)d_in[2];
    const float* b1  = (const float*)d_in[3];
    const float* W2  = (const float*)d_in[4];
    const float* b2  = (const float*)d_in[5];
    const float* Wfc = (const float*)d_in[6];
    const float* bfc = (const float*)d_in[7];
    float* out = (float*)d_out;

    int N = in_sizes[0] / 128;
    int E = in_sizes[1] / 2;
    if (N > MAXN) N = MAXN;
    if (E > MAXE) E = MAXE;

    const int TB = 256;
    int nb_N  = (N + TB - 1) / TB;
    int nb_E  = (E + TB - 1) / TB;
    int nb_GM = (N + 127) / 128;
    int nb_AG = (N + 7) / 8;

    zero_detect<<<nb_N, TB>>>((const int*)ei, N);
    place_direct<<<nb_E, TB>>>(ei, E);
    dinv_kernel<<<nb_N, TB>>>(N);

    // layer 1
    gemm_mma<128, false><<<nb_GM, 256>>>(x, W1, N);
    aggregate_kernel<false><<<nb_AG, 256>>>(b1, nullptr, nullptr, nullptr, N);

    // layer 2
    gemm_mma<64, true><<<nb_GM, 256>>>(nullptr, W2, N);
    aggregate_kernel<true><<<nb_AG, 256>>>(b2, Wfc, bfc, out, N);
}